// round 11
// baseline (speedup 1.0000x reference)
#include <cuda_runtime.h>
#include <math.h>

// BatchHardTripletLoss on GB300.
// inputs: d_in[0] = embeddings float32 [8192,128]
//         d_in[1] = labels (int32 in practice: JAX x64 is disabled, so the
//                   reference's jnp.int64 silently becomes int32; we probe
//                   the buffer layout at runtime to be safe)
// output: d_out[0] = scalar float32 loss
//
// loss = mean_i relu( max_{j: lab_j==lab_i} dist(i,j) - min_{j: lab_j!=lab_i} dist(i,j) + 1 )

#define BB 8192
#define DD 128
#define BM 128
#define BN 128
#define BK 16
#define TM 8
#define TN 8
#define NCOLGROUPS 8
#define CT_PER_GROUP ((BB / BN) / NCOLGROUPS)   // 8 column tiles per block

// Scratch (no allocations allowed; __device__ globals are the sanctioned path)
__device__ float        g_sq [BB];
__device__ int          g_lab[BB];
__device__ unsigned int g_hp2[BB];   // float bits of max same-class d^2 (>=0; uint order == float order)
__device__ unsigned int g_hn2[BB];   // float bits of min diff-class d^2 (init +inf)
__device__ int          g_is64;      // 1 if labels buffer is int64-layout

// ---------------------------------------------------------------------------
// Kernel 0: probe label dtype. Reads only the first 8192 32-bit words, which
// is in-bounds for both int32[8192] (32KB) and int64[8192] (64KB) layouts.
// int64-LE with values 0..9 => every odd word is the zero high-half.
// int32 random labels 0..9  => some odd word is nonzero (P(fail) ~ 0.1^4096).
// ---------------------------------------------------------------------------
__global__ void probe_kernel(const int* __restrict__ lab32) {
    __shared__ int bad;
    if (threadIdx.x == 0) bad = 0;
    __syncthreads();
    int any = 0;
    for (int i = 1 + 2 * threadIdx.x; i < BB; i += 2 * blockDim.x)
        any |= (lab32[i] != 0);
    if (any) atomicOr(&bad, 1);
    __syncthreads();
    if (threadIdx.x == 0) g_is64 = bad ? 0 : 1;
}

// ---------------------------------------------------------------------------
// Kernel 1: row squared norms, labels -> int, re-init reduction state.
// One warp per row; 8192/8 = 1024 blocks x 256 threads.
// ---------------------------------------------------------------------------
__global__ void prep_kernel(const float* __restrict__ emb,
                            const int* __restrict__ lab32) {
    int row  = blockIdx.x * 8 + (threadIdx.x >> 5);
    int lane = threadIdx.x & 31;
    float4 v = reinterpret_cast<const float4*>(emb)[row * (DD / 4) + lane];
    float s = v.x * v.x + v.y * v.y + v.z * v.z + v.w * v.w;
    #pragma unroll
    for (int o = 16; o; o >>= 1) s += __shfl_xor_sync(0xffffffffu, s, o);
    if (lane == 0) {
        g_sq[row]  = s;
        g_lab[row] = g_is64 ? lab32[2 * row] : lab32[row];
        g_hp2[row] = 0u;           // self-pair has dist 0, so max >= 0 always
        g_hn2[row] = 0x7f800000u;  // +inf
    }
}

// ---------------------------------------------------------------------------
// Kernel 2: fused E@E^T tile GEMM (fp32) + masked row max/min of d^2.
// Block tile 128x128, 256 threads, 8x8 micro-tiles, BK=16, A/B transposed in
// smem. grid = (64 row tiles, 8 column groups); each block sweeps 8 col tiles.
// ---------------------------------------------------------------------------
__global__ __launch_bounds__(256, 2)
void dist_kernel(const float* __restrict__ emb) {
    __shared__ float As[BK][BM];   // [k][row]   (2048 floats, reused for reduction)
    __shared__ float Bs[BK][BN];   // [k][col]
    __shared__ float s_sqc[BN];
    __shared__ int   s_labc[BN];

    const int tid = threadIdx.x;
    const int tx  = tid & 15;   // 0..15 -> 8 columns each
    const int ty  = tid >> 4;   // 0..15 -> 8 rows each
    const int rowBase  = blockIdx.x * BM;
    const int colTile0 = blockIdx.y * CT_PER_GROUP;

    // Per-thread row constants
    const int r0 = rowBase + ty * TM;
    float sqr[TM];
    int   labr[TM];
    #pragma unroll
    for (int i = 0; i < TM; i++) { sqr[i] = g_sq[r0 + i]; labr[i] = g_lab[r0 + i]; }

    float hp2[TM], hn2[TM];
    #pragma unroll
    for (int i = 0; i < TM; i++) { hp2[i] = 0.0f; hn2[i] = INFINITY; }

    // Coalesced gmem->smem mapping: each thread loads two float4 (rows r, r+64)
    const int lrow = tid >> 2;          // 0..63
    const int lk4  = (tid & 3) * 4;     // 0,4,8,12

    for (int ct = 0; ct < CT_PER_GROUP; ct++) {
        const int colBase = (colTile0 + ct) * BN;

        __syncthreads();   // previous tile's epilogue reads of s_sqc/s_labc done
        if (tid < BN) { s_sqc[tid] = g_sq[colBase + tid]; s_labc[tid] = g_lab[colBase + tid]; }

        float acc[TM][TN];
        #pragma unroll
        for (int i = 0; i < TM; i++)
            #pragma unroll
            for (int j = 0; j < TN; j++) acc[i][j] = 0.0f;

        for (int kk = 0; kk < DD; kk += BK) {
            __syncthreads();   // previous k-chunk's smem reads done
            #pragma unroll
            for (int half = 0; half < 2; half++) {
                int r = lrow + half * 64;
                float4 av = *reinterpret_cast<const float4*>(emb + (rowBase + r) * DD + kk + lk4);
                As[lk4 + 0][r] = av.x; As[lk4 + 1][r] = av.y;
                As[lk4 + 2][r] = av.z; As[lk4 + 3][r] = av.w;
                float4 bv = *reinterpret_cast<const float4*>(emb + (colBase + r) * DD + kk + lk4);
                Bs[lk4 + 0][r] = bv.x; Bs[lk4 + 1][r] = bv.y;
                Bs[lk4 + 2][r] = bv.z; Bs[lk4 + 3][r] = bv.w;
            }
            __syncthreads();

            #pragma unroll
            for (int k = 0; k < BK; k++) {
                float4 a0 = *reinterpret_cast<const float4*>(&As[k][ty * TM]);
                float4 a1 = *reinterpret_cast<const float4*>(&As[k][ty * TM + 4]);
                float4 b0 = *reinterpret_cast<const float4*>(&Bs[k][tx * TN]);
                float4 b1 = *reinterpret_cast<const float4*>(&Bs[k][tx * TN + 4]);
                float a[TM] = {a0.x, a0.y, a0.z, a0.w, a1.x, a1.y, a1.z, a1.w};
                float b[TN] = {b0.x, b0.y, b0.z, b0.w, b1.x, b1.y, b1.z, b1.w};
                #pragma unroll
                for (int i = 0; i < TM; i++)
                    #pragma unroll
                    for (int j = 0; j < TN; j++)
                        acc[i][j] += a[i] * b[j];
            }
        }

        // Epilogue: d^2 = |e_i|^2 + |e_j|^2 - 2 dot, clamp 0, masked max/min.
        #pragma unroll
        for (int j = 0; j < TN; j++) {
            const int c = tx * TN + j;
            const float sqc = s_sqc[c];
            const int   lbc = s_labc[c];
            #pragma unroll
            for (int i = 0; i < TM; i++) {
                float d2 = fmaxf(sqr[i] + sqc - 2.0f * acc[i][j], 0.0f);
                bool same = (labr[i] == lbc);
                hp2[i] = same ? fmaxf(hp2[i], d2) : hp2[i];
                hn2[i] = same ? hn2[i] : fminf(hn2[i], d2);
            }
        }
    }

    // Block reduction over the 16 tx-threads sharing each row, then one atomic/row.
    __syncthreads();
    float* redp = &As[0][0];   // 2048 floats = 128 rows x 16
    float* redn = &Bs[0][0];
    #pragma unroll
    for (int i = 0; i < TM; i++) {
        redp[(ty * TM + i) * 16 + tx] = hp2[i];
        redn[(ty * TM + i) * 16 + tx] = hn2[i];
    }
    __syncthreads();
    if (tid < BM) {
        float mx = 0.0f, mn = INFINITY;
        #pragma unroll
        for (int t = 0; t < 16; t++) {
            mx = fmaxf(mx, redp[tid * 16 + t]);
            mn = fminf(mn, redn[tid * 16 + t]);
        }
        atomicMax(&g_hp2[rowBase + tid], __float_as_uint(mx));
        atomicMin(&g_hn2[rowBase + tid], __float_as_uint(mn));
    }
}

// ---------------------------------------------------------------------------
// Kernel 3: per-anchor loss + deterministic reduction to the scalar.
// ---------------------------------------------------------------------------
__global__ void finish_kernel(float* __restrict__ out) {
    __shared__ float ssum[32];
    const int tid = threadIdx.x;   // 1024 threads
    float s = 0.0f;
    for (int i = tid; i < BB; i += 1024) {
        float hp = sqrtf(__uint_as_float(g_hp2[i]));
        float hn = sqrtf(__uint_as_float(g_hn2[i]));   // +inf if no negatives -> relu gives 0
        s += fmaxf(hp - hn + 1.0f, 0.0f);
    }
    #pragma unroll
    for (int o = 16; o; o >>= 1) s += __shfl_xor_sync(0xffffffffu, s, o);
    if ((tid & 31) == 0) ssum[tid >> 5] = s;
    __syncthreads();
    if (tid < 32) {
        float v = ssum[tid];
        #pragma unroll
        for (int o = 16; o; o >>= 1) v += __shfl_xor_sync(0xffffffffu, v, o);
        if (tid == 0) out[0] = v / (float)BB;
    }
}

// ---------------------------------------------------------------------------
extern "C" void kernel_launch(void* const* d_in, const int* in_sizes, int n_in,
                              void* d_out, int out_size) {
    const float* emb   = (const float*)d_in[0];
    const int*   lab32 = (const int*)d_in[1];
    float*       out   = (float*)d_out;
    (void)in_sizes; (void)n_in; (void)out_size;

    probe_kernel<<<1, 256>>>(lab32);
    prep_kernel<<<BB / 8, 256>>>(emb, lab32);
    dim3 grid(BB / BM, NCOLGROUPS);
    dist_kernel<<<grid, 256>>>(emb);
    finish_kernel<<<1, 1024>>>(out);
}

// round 16
// speedup vs baseline: 3.3820x; 3.3820x over previous
#include <cuda_runtime.h>
#include <math.h>
#include <stdint.h>

// BatchHardTripletLoss on GB300 — legacy tensor-core path (mma.sync tf32),
// since the harness's compute_103 PTX target rejects all tcgen05/sm_103a-only
// instructions. TF32 numerics validated empirically in R8 (delta 7.5e-7 rel).
//
// inputs: d_in[0] = embeddings float32 [8192,128]
//         d_in[1] = labels (int32 in practice; runtime layout probe kept)
// output: d_out[0] = scalar float32 loss

#define BB 8192
#define DD 128
#define BM 128
#define BN 128
#define NCOLGROUPS 8
#define CT_PER_GROUP ((BB / BN) / NCOLGROUPS)   // 8 column tiles per block
#define LDA 132                                  // smem row stride (floats), conflict-free

// smem layout in floats
#define OF_A    0
#define OF_B    (128 * LDA)            // 16896
#define OF_SQC  (2 * 128 * LDA)        // 33792  (1024 floats: all cols of this group)
#define OF_LABC (OF_SQC + 1024)        // 34816  (1024 ints)
#define SM_FLOATS (OF_LABC + 1024)     // 35840 floats = 143360 bytes

// ---------------------------------------------------------------------------
// Device scratch
// ---------------------------------------------------------------------------
__device__ float        g_embr[BB * DD];   // tf32-rounded embeddings (4 MB)
__device__ float        g_sq [BB];
__device__ int          g_lab[BB];
__device__ unsigned int g_hp2[BB];   // float bits of max same-class d^2
__device__ unsigned int g_hn2[BB];   // float bits of min diff-class d^2 (init +inf)
__device__ float        g_partial[64];
__device__ int          g_is64;

static __device__ __forceinline__ float to_tf32(float x) {
    float r;
    asm("cvt.rna.tf32.f32 %0, %1;" : "=f"(r) : "f"(x));
    return r;
}

#define MMA_TF32(c, a, b) \
    asm volatile( \
        "mma.sync.aligned.m16n8k8.row.col.f32.tf32.tf32.f32 " \
        "{%0,%1,%2,%3}, {%4,%5,%6,%7}, {%8,%9}, {%0,%1,%2,%3};" \
        : "+f"((c)[0]), "+f"((c)[1]), "+f"((c)[2]), "+f"((c)[3]) \
        : "r"((a)[0]), "r"((a)[1]), "r"((a)[2]), "r"((a)[3]), \
          "r"((b)[0]), "r"((b)[1]))

// ---------------------------------------------------------------------------
// Kernel 0: probe label dtype (int32 vs int64-LE). In-bounds for both layouts.
// ---------------------------------------------------------------------------
__global__ void probe_kernel(const int* __restrict__ lab32) {
    __shared__ int bad;
    if (threadIdx.x == 0) bad = 0;
    __syncthreads();
    int any = 0;
    for (int i = 1 + 2 * threadIdx.x; i < BB; i += 2 * blockDim.x)
        any |= (lab32[i] != 0);
    if (any) atomicOr(&bad, 1);
    __syncthreads();
    if (threadIdx.x == 0) g_is64 = bad ? 0 : 1;
}

// ---------------------------------------------------------------------------
// Kernel 1: row squared norms (exact fp32), tf32-rounded embedding copy,
// labels, reduction-state re-init. One warp per row.
// ---------------------------------------------------------------------------
__global__ void prep_kernel(const float* __restrict__ emb,
                            const int* __restrict__ lab32) {
    int row  = blockIdx.x * 8 + (threadIdx.x >> 5);
    int lane = threadIdx.x & 31;
    float4 v = reinterpret_cast<const float4*>(emb)[row * (DD / 4) + lane];
    float s = v.x * v.x + v.y * v.y + v.z * v.z + v.w * v.w;   // exact fp32 norms
    float4 w;
    w.x = to_tf32(v.x); w.y = to_tf32(v.y); w.z = to_tf32(v.z); w.w = to_tf32(v.w);
    reinterpret_cast<float4*>(g_embr)[row * (DD / 4) + lane] = w;
    #pragma unroll
    for (int o = 16; o; o >>= 1) s += __shfl_xor_sync(0xffffffffu, s, o);
    if (lane == 0) {
        g_sq[row]  = s;
        g_lab[row] = g_is64 ? lab32[2 * row] : lab32[row];
        g_hp2[row] = 0u;
        g_hn2[row] = 0x7f800000u;
    }
}

// ---------------------------------------------------------------------------
// Kernel 2: mma.sync tf32 E@E^T (128x128 tiles, K=128) fused with masked
// row max/min of d^2. grid = (64 row tiles, 8 col groups) x 256 threads.
// Warps in 2x4 layout: warp tile 64(M) x 32(N).
// ---------------------------------------------------------------------------
__global__ __launch_bounds__(256, 1)
void dist_kernel() {
    extern __shared__ float sm[];
    float*        As   = sm + OF_A;
    float*        Bs   = sm + OF_B;
    float*        sqc  = sm + OF_SQC;
    int*          labc = reinterpret_cast<int*>(sm + OF_LABC);
    const unsigned* Au = reinterpret_cast<const unsigned*>(As);
    const unsigned* Bu = reinterpret_cast<const unsigned*>(Bs);

    const int tid  = threadIdx.x;
    const int wid  = tid >> 5;
    const int lane = tid & 31;
    const int g    = lane >> 2;     // group id 0..7
    const int t    = lane & 3;      // thread-in-group 0..3
    const int wm   = wid & 1;       // 0..1 : 64-row slab
    const int wn   = wid >> 1;      // 0..3 : 32-col slab
    const int rowBase  = blockIdx.x * BM;
    const int colTile0 = blockIdx.y * CT_PER_GROUP;
    const int colBase0 = colTile0 * BN;           // 1024-aligned column window

    // ---- stage A tile (this block's rows) + all 1024 col sq/labels ----
    #pragma unroll
    for (int it = 0; it < 16; it++) {
        int e   = tid + 256 * it;                 // 4096 float4s
        int row = e >> 5;
        int k4  = e & 31;
        float4 v = reinterpret_cast<const float4*>(g_embr + (rowBase + row) * DD)[k4];
        *reinterpret_cast<float4*>(As + row * LDA + k4 * 4) = v;
    }
    #pragma unroll
    for (int r = 0; r < 4; r++) {
        int idx = tid + 256 * r;
        sqc[idx]  = g_sq[colBase0 + idx];
        labc[idx] = g_lab[colBase0 + idx];
    }

    // per-thread row constants (8 row slots: 4 i-tiles x 2 halves)
    float sqr8[4][2];
    int   labr8[4][2];
    #pragma unroll
    for (int i = 0; i < 4; i++)
        #pragma unroll
        for (int h = 0; h < 2; h++) {
            int r = rowBase + wm * 64 + i * 16 + g + 8 * h;
            sqr8[i][h]  = g_sq[r];
            labr8[i][h] = g_lab[r];
        }

    float hp2[4][2], hn2[4][2];
    #pragma unroll
    for (int i = 0; i < 4; i++)
        #pragma unroll
        for (int h = 0; h < 2; h++) { hp2[i][h] = 0.0f; hn2[i][h] = INFINITY; }

    __syncthreads();

    // ---- software pipeline: prefetch B tile ct into regs, STS at loop top ----
    float4 pref[16];
    #pragma unroll
    for (int it = 0; it < 16; it++) {
        int e = tid + 256 * it;
        pref[it] = reinterpret_cast<const float4*>(g_embr + colBase0 * DD)[e];
    }

    for (int ct = 0; ct < CT_PER_GROUP; ct++) {
        // store prefetched tile
        #pragma unroll
        for (int it = 0; it < 16; it++) {
            int e   = tid + 256 * it;
            int row = e >> 5;
            int k4  = e & 31;
            *reinterpret_cast<float4*>(Bs + row * LDA + k4 * 4) = pref[it];
        }
        __syncthreads();

        // prefetch next tile (latency hidden behind the mma loop)
        if (ct + 1 < CT_PER_GROUP) {
            const float* src = g_embr + (colBase0 + (ct + 1) * BN) * DD;
            #pragma unroll
            for (int it = 0; it < 16; it++) {
                int e = tid + 256 * it;
                pref[it] = reinterpret_cast<const float4*>(src)[e];
            }
        }

        float acc[4][4][4];
        #pragma unroll
        for (int i = 0; i < 4; i++)
            #pragma unroll
            for (int j = 0; j < 4; j++)
                #pragma unroll
                for (int q = 0; q < 4; q++) acc[i][j][q] = 0.0f;

        for (int s = 0; s < 16; s++) {            // K = 16 x k8
            const int c0 = s * 8 + t;
            unsigned a[4][4], b[4][2];
            #pragma unroll
            for (int i = 0; i < 4; i++) {
                int r = wm * 64 + i * 16 + g;
                a[i][0] = Au[r * LDA + c0];
                a[i][1] = Au[(r + 8) * LDA + c0];
                a[i][2] = Au[r * LDA + c0 + 4];
                a[i][3] = Au[(r + 8) * LDA + c0 + 4];
            }
            #pragma unroll
            for (int j = 0; j < 4; j++) {
                int rb = wn * 32 + j * 8 + g;
                b[j][0] = Bu[rb * LDA + c0];
                b[j][1] = Bu[rb * LDA + c0 + 4];
            }
            #pragma unroll
            for (int i = 0; i < 4; i++)
                #pragma unroll
                for (int j = 0; j < 4; j++)
                    MMA_TF32(acc[i][j], a[i], b[j]);
        }
        __syncthreads();   // Bs consumed; safe to overwrite next iteration

        // fused epilogue: d^2 + masked max/min, straight from accumulators
        const float* sq_c = sqc + ct * BN;
        const int*   lb_c = labc + ct * BN;
        #pragma unroll
        for (int j = 0; j < 4; j++) {
            int cb = wn * 32 + j * 8 + 2 * t;
            float s0 = sq_c[cb],  s1 = sq_c[cb + 1];
            int   l0 = lb_c[cb],  l1 = lb_c[cb + 1];
            #pragma unroll
            for (int i = 0; i < 4; i++) {
                #pragma unroll
                for (int h = 0; h < 2; h++) {
                    float d2a = fmaxf(sqr8[i][h] + s0 - 2.0f * acc[i][j][2 * h],     0.0f);
                    float d2b = fmaxf(sqr8[i][h] + s1 - 2.0f * acc[i][j][2 * h + 1], 0.0f);
                    bool sa = (labr8[i][h] == l0);
                    bool sb = (labr8[i][h] == l1);
                    hp2[i][h] = fmaxf(hp2[i][h], sa ? d2a : 0.0f);
                    hn2[i][h] = fminf(hn2[i][h], sa ? INFINITY : d2a);
                    hp2[i][h] = fmaxf(hp2[i][h], sb ? d2b : 0.0f);
                    hn2[i][h] = fminf(hn2[i][h], sb ? INFINITY : d2b);
                }
            }
        }
    }

    // ---- reduction: quad-shuffle over t, smem over wn, one atomic per row ----
    __syncthreads();           // done with As/Bs; reuse As as reduction scratch
    float* redp = As;          // 128 x 4
    float* redn = As + 512;
    #pragma unroll
    for (int i = 0; i < 4; i++)
        #pragma unroll
        for (int h = 0; h < 2; h++) {
            float mp = hp2[i][h], mn = hn2[i][h];
            mp = fmaxf(mp, __shfl_xor_sync(0xffffffffu, mp, 1));
            mp = fmaxf(mp, __shfl_xor_sync(0xffffffffu, mp, 2));
            mn = fminf(mn, __shfl_xor_sync(0xffffffffu, mn, 1));
            mn = fminf(mn, __shfl_xor_sync(0xffffffffu, mn, 2));
            if (t == 0) {
                int r = wm * 64 + i * 16 + g + 8 * h;
                redp[r * 4 + wn] = mp;
                redn[r * 4 + wn] = mn;
            }
        }
    __syncthreads();
    if (tid < BM) {
        float mx = redp[tid * 4], mn = redn[tid * 4];
        #pragma unroll
        for (int w = 1; w < 4; w++) {
            mx = fmaxf(mx, redp[tid * 4 + w]);
            mn = fminf(mn, redn[tid * 4 + w]);
        }
        atomicMax(&g_hp2[rowBase + tid], __float_as_uint(mx));
        atomicMin(&g_hn2[rowBase + tid], __float_as_uint(mn));
    }
}

// ---------------------------------------------------------------------------
// Kernel 3a/3b: per-anchor loss, two-stage deterministic reduction.
// ---------------------------------------------------------------------------
__global__ void finishA_kernel() {
    __shared__ float ssum[4];
    const int tid = threadIdx.x;                     // 128 threads, 64 blocks
    const int i = blockIdx.x * 128 + tid;
    float hp = sqrtf(__uint_as_float(g_hp2[i]));
    float hn = sqrtf(__uint_as_float(g_hn2[i]));     // +inf -> relu 0
    float s  = fmaxf(hp - hn + 1.0f, 0.0f);
    #pragma unroll
    for (int o = 16; o; o >>= 1) s += __shfl_xor_sync(0xffffffffu, s, o);
    if ((tid & 31) == 0) ssum[tid >> 5] = s;
    __syncthreads();
    if (tid == 0)
        g_partial[blockIdx.x] = ssum[0] + ssum[1] + ssum[2] + ssum[3];
}

__global__ void finishB_kernel(float* __restrict__ out) {
    const int tid = threadIdx.x;                     // 32 threads
    float s = g_partial[tid] + g_partial[tid + 32];
    #pragma unroll
    for (int o = 16; o; o >>= 1) s += __shfl_xor_sync(0xffffffffu, s, o);
    if (tid == 0) out[0] = s / (float)BB;
}

// ---------------------------------------------------------------------------
extern "C" void kernel_launch(void* const* d_in, const int* in_sizes, int n_in,
                              void* d_out, int out_size) {
    const float* emb   = (const float*)d_in[0];
    const int*   lab32 = (const int*)d_in[1];
    float*       out   = (float*)d_out;
    (void)in_sizes; (void)n_in; (void)out_size;

    cudaFuncSetAttribute(dist_kernel, cudaFuncAttributeMaxDynamicSharedMemorySize,
                         SM_FLOATS * 4);

    probe_kernel<<<1, 256>>>(lab32);
    prep_kernel<<<BB / 8, 256>>>(emb, lab32);
    dim3 grid(BB / BM, NCOLGROUPS);
    dist_kernel<<<grid, 256, SM_FLOATS * 4>>>();
    finishA_kernel<<<64, 128>>>();
    finishB_kernel<<<1, 32>>>(out);
}